// round 7
// baseline (speedup 1.0000x reference)
#include <cuda_runtime.h>
#include <cuda_bf16.h>
#include <math_constants.h>

// Problem shape (fixed by dataset)
#define NN 100000
#define NE 1600000
#define INF_ 128
#define OUTF 64
#define SCAN_NB 391          // ceil(NN/256)

// ---------------- device scratch (static: no runtime allocation) -------------
// NOTE lifecycle: g_deg is zero at every kernel_launch entry — zero-initialized
// at load, and re-zeroed by k_aggregate at the end of every executed call
// (graph capture does not execute, so the invariant holds across replays).
__device__ float g_ft[(size_t)NN * OUTF];       // projected features  [N,64]
__device__ int   g_deg[NN];                     // in-degree histogram
__device__ int   g_offs[NN + 1];                // CSR offsets by dst
__device__ int   g_cursor[NN];                  // scatter cursors
__device__ int   g_csr_src[NE];                 // src node per CSR slot
__device__ unsigned long long g_state[SCAN_NB]; // lookback: (status<<32)|sum

__device__ __forceinline__ int clampidx(int v) {
    unsigned u = (unsigned)v;
    return (u < (unsigned)NN) ? v : 0;
}

// packed f32x2 helpers (Blackwell: FFMA2 only reachable from PTX)
__device__ __forceinline__ unsigned long long pack2(float lo, float hi) {
    unsigned long long r;
    asm("mov.b64 %0, {%1, %2};" : "=l"(r) : "f"(lo), "f"(hi));
    return r;
}
__device__ __forceinline__ void unpack2(unsigned long long v, float& lo, float& hi) {
    asm("mov.b64 {%0, %1}, %2;" : "=f"(lo), "=f"(hi) : "l"(v));
}
__device__ __forceinline__ void fma2(unsigned long long& d,
                                     unsigned long long a, unsigned long long b) {
    asm("fma.rn.f32x2 %0, %1, %2, %0;" : "+l"(d) : "l"(a), "l"(b));
}

// ---------------- K1: in-degree histogram + scan-state reset -----------------
__global__ __launch_bounds__(256) void k_deg(const int* __restrict__ dst) {
    int t = blockIdx.x * blockDim.x + threadIdx.x;
    if (t < SCAN_NB) g_state[t] = 0ull;       // consumed by k_scan (next launch)
    if (t >= NE / 4) return;
    int4 d4 = ((const int4*)dst)[t];
    atomicAdd(&g_deg[clampidx(d4.x)], 1);
    atomicAdd(&g_deg[clampidx(d4.y)], 1);
    atomicAdd(&g_deg[clampidx(d4.z)], 1);
    atomicAdd(&g_deg[clampidx(d4.w)], 1);
}

// ---------------- K2: single-pass decoupled-lookback exclusive scan ----------
__global__ __launch_bounds__(256) void k_scan() {
    __shared__ int wsum[8];
    __shared__ int bprefix;
    int b = blockIdx.x;
    int tid = threadIdx.x;
    int lane = tid & 31;
    int wid = tid >> 5;
    int i = b * 256 + tid;

    int v = (i < NN) ? g_deg[i] : 0;
    int x = v;
#pragma unroll
    for (int o = 1; o < 32; o <<= 1) {
        int t = __shfl_up_sync(0xffffffffu, x, o);
        if (lane >= o) x += t;
    }
    if (lane == 31) wsum[wid] = x;
    __syncthreads();
    if (wid == 0) {
        int y = (lane < 8) ? wsum[lane] : 0;
#pragma unroll
        for (int o = 1; o < 8; o <<= 1) {
            int t = __shfl_up_sync(0xffffffffu, y, o);
            if (lane >= o) y += t;
        }
        if (lane < 8) wsum[lane] = y;
    }
    __syncthreads();
    int incl = x + ((wid > 0) ? wsum[wid - 1] : 0);
    int btotal = wsum[7];

    if (tid == 0) {
        if (b == 0) {
            atomicExch(&g_state[0], (2ull << 32) | (unsigned)btotal);
            bprefix = 0;
        } else {
            atomicExch(&g_state[b], (1ull << 32) | (unsigned)btotal);
            long long ex = 0;
            int pred = b - 1;
            while (true) {
                unsigned long long s =
                    *((volatile unsigned long long*)&g_state[pred]);
                unsigned st = (unsigned)(s >> 32);
                if (st == 0) continue;
                ex += (unsigned)s;
                if (st == 2) break;
                pred--;
            }
            atomicExch(&g_state[b], (2ull << 32) | (unsigned)(ex + btotal));
            bprefix = (int)ex;
        }
    }
    __syncthreads();

    if (i < NN) {
        int o = bprefix + incl - v;
        g_offs[i] = o;
        g_cursor[i] = o;
    }
    if (i == 0) g_offs[NN] = NE;
}

// ---------------- K3: scatter into CSR (4 atomics batched -> 4 stores) -------
__global__ __launch_bounds__(256) void k_scatter(const int* __restrict__ src,
                                                 const int* __restrict__ dst) {
    int t = blockIdx.x * blockDim.x + threadIdx.x;
    if (t >= NE / 4) return;
    int4 s4 = ((const int4*)src)[t];
    int4 d4 = ((const int4*)dst)[t];
    int p0 = atomicAdd(&g_cursor[clampidx(d4.x)], 1);
    int p1 = atomicAdd(&g_cursor[clampidx(d4.y)], 1);
    int p2 = atomicAdd(&g_cursor[clampidx(d4.z)], 1);
    int p3 = atomicAdd(&g_cursor[clampidx(d4.w)], 1);
    g_csr_src[p0] = clampidx(s4.x);
    g_csr_src[p1] = clampidx(s4.y);
    g_csr_src[p2] = clampidx(s4.z);
    g_csr_src[p3] = clampidx(s4.w);
}

// ---------------- K4: ft = feat @ W  (128x64 tile, 4x8/thread, FFMA2) --------
// 256 threads, 2 blocks/SM. Thread: 4 rows x 8 cols. Per 4-k group:
// 4 LDG.128 (feat, broadcast-coalesced) + 8 LDS.128 (W) for 128 FMAs.
__global__ __launch_bounds__(256, 2) void k_gemm(const float* __restrict__ feat,
                                                 const float* __restrict__ Wm) {
    __shared__ float wsm[INF_ * OUTF];   // 32 KB, row-major [k][c]
    int tid = threadIdx.x;

    for (int i = tid; i < (INF_ * OUTF) / 4; i += 256)
        ((float4*)wsm)[i] = ((const float4*)Wm)[i];
    __syncthreads();

    int rg = tid >> 3;                         // 0..31 row group
    int c0 = (tid & 7) * 8;                    // 0,8,...,56
    int row0 = blockIdx.x * 128 + rg * 4;      // 4 rows

    int r[4];
#pragma unroll
    for (int i = 0; i < 4; i++) r[i] = (row0 + i < NN) ? row0 + i : 0;

    unsigned long long acc[4][4];              // [row][colpair]
#pragma unroll
    for (int i = 0; i < 4; i++)
#pragma unroll
        for (int j = 0; j < 4; j++) acc[i][j] = 0ull;

    for (int kk = 0; kk < INF_ / 4; kk++) {
        // stage 16 weight pairs (4 k-steps x 8 cols)
        unsigned long long b[4][4];
#pragma unroll
        for (int j = 0; j < 4; j++) {
            float4 wa = *(const float4*)(wsm + (kk * 4 + j) * OUTF + c0);
            float4 wb = *(const float4*)(wsm + (kk * 4 + j) * OUTF + c0 + 4);
            b[j][0] = pack2(wa.x, wa.y);
            b[j][1] = pack2(wa.z, wa.w);
            b[j][2] = pack2(wb.x, wb.y);
            b[j][3] = pack2(wb.z, wb.w);
        }
        float4 fr[4];
#pragma unroll
        for (int i = 0; i < 4; i++)
            fr[i] = ((const float4*)(feat + (size_t)r[i] * INF_))[kk];
#pragma unroll
        for (int i = 0; i < 4; i++) {
#pragma unroll
            for (int j = 0; j < 4; j++) {
                float f = (j == 0) ? fr[i].x : (j == 1) ? fr[i].y
                         : (j == 2) ? fr[i].z : fr[i].w;
                unsigned long long a2 = pack2(f, f);
                fma2(acc[i][0], a2, b[j][0]);
                fma2(acc[i][1], a2, b[j][1]);
                fma2(acc[i][2], a2, b[j][2]);
                fma2(acc[i][3], a2, b[j][3]);
            }
        }
    }

#pragma unroll
    for (int i = 0; i < 4; i++) {
        int row = row0 + i;
        if (row < NN) {
            float4 o1, o2;
            unpack2(acc[i][0], o1.x, o1.y);
            unpack2(acc[i][1], o1.z, o1.w);
            unpack2(acc[i][2], o2.x, o2.y);
            unpack2(acc[i][3], o2.z, o2.w);
            *(float4*)(g_ft + (size_t)row * OUTF + c0) = o1;
            *(float4*)(g_ft + (size_t)row * OUTF + c0 + 4) = o2;
        }
    }
}

// ---------------- K5: fused score + ONLINE softmax + aggregation -------------
// One warp per node; lane l owns output dims [2l, 2l+1].
// Warp dot-reduce via half-warp fold: 6 SHFLs per 2 edges; 4-edge unroll.
__global__ __launch_bounds__(256) void k_aggregate(float* __restrict__ out) {
    int w = threadIdx.x >> 5;
    int lane = threadIdx.x & 31;
    int node = blockIdx.x * 8 + w;
    if (node >= NN) return;

    int lo = g_offs[node];
    int hi = g_offs[node + 1];
    if (lane == 0) g_deg[node] = 0;          // reset for next replay

    float2 df = *(const float2*)(g_ft + (size_t)node * OUTF + lane * 2);

    float m = -CUDART_INF_F;
    float s = 0.f;
    float2 acc = make_float2(0.f, 0.f);
    bool hi16 = (lane & 16) != 0;

    int i = lo;
    for (; i + 3 < hi; i += 4) {
        int s0 = g_csr_src[i];
        int s1 = g_csr_src[i + 1];
        int s2 = g_csr_src[i + 2];
        int s3 = g_csr_src[i + 3];
        float2 f0 = *(const float2*)(g_ft + (size_t)s0 * OUTF + lane * 2);
        float2 f1 = *(const float2*)(g_ft + (size_t)s1 * OUTF + lane * 2);
        float2 f2 = *(const float2*)(g_ft + (size_t)s2 * OUTF + lane * 2);
        float2 f3 = *(const float2*)(g_ft + (size_t)s3 * OUTF + lane * 2);
        float p0 = f0.x * df.x + f0.y * df.y;
        float p1 = f1.x * df.x + f1.y * df.y;
        float p2 = f2.x * df.x + f2.y * df.y;
        float p3 = f3.x * df.x + f3.y * df.y;

        // fold chains: low half reduces even edge, high half odd edge
        float uA = hi16 ? p1 : p0;
        float uB = hi16 ? p3 : p2;
        uA += __shfl_xor_sync(0xffffffffu, hi16 ? p0 : p1, 16);
        uB += __shfl_xor_sync(0xffffffffu, hi16 ? p2 : p3, 16);
#pragma unroll
        for (int o = 8; o; o >>= 1) {
            uA += __shfl_xor_sync(0xffffffffu, uA, o);
            uB += __shfl_xor_sync(0xffffffffu, uB, o);
        }
        float oA = __shfl_xor_sync(0xffffffffu, uA, 16);
        float oB = __shfl_xor_sync(0xffffffffu, uB, 16);
        float a0 = hi16 ? oA : uA;
        float a1 = hi16 ? uA : oA;
        float a2 = hi16 ? oB : uB;
        float a3 = hi16 ? uB : oB;

        float mn = fmaxf(fmaxf(a0, a1), fmaxf(a2, a3));
        if (mn > m) {                          // warp-uniform branch
            float rsc = __expf(m - mn);        // first hit: exp(-inf)=0
            s *= rsc; acc.x *= rsc; acc.y *= rsc;
            m = mn;
        }
        float w0 = __expf(a0 - m);
        float w1 = __expf(a1 - m);
        float w2 = __expf(a2 - m);
        float w3 = __expf(a3 - m);
        s += (w0 + w1) + (w2 + w3);
        acc.x += w0 * f0.x + w1 * f1.x + w2 * f2.x + w3 * f3.x;
        acc.y += w0 * f0.y + w1 * f1.y + w2 * f2.y + w3 * f3.y;
    }
    // remainder (0-3 edges): plain butterfly
    for (; i < hi; i++) {
        int s0 = g_csr_src[i];
        float2 f0 = *(const float2*)(g_ft + (size_t)s0 * OUTF + lane * 2);
        float p0 = f0.x * df.x + f0.y * df.y;
#pragma unroll
        for (int o = 16; o; o >>= 1) p0 += __shfl_xor_sync(0xffffffffu, p0, o);
        if (p0 > m) {
            float rsc = __expf(m - p0);
            s *= rsc; acc.x *= rsc; acc.y *= rsc;
            m = p0;
        }
        float w0 = __expf(p0 - m);
        s += w0;
        acc.x += w0 * f0.x;
        acc.y += w0 * f0.y;
    }

    if (hi > lo) {
        float inv = 1.f / s;
        acc.x *= inv;
        acc.y *= inv;
    }
    *(float2*)(out + (size_t)node * OUTF + lane * 2) = acc;
}

// ---------------- launch ------------------------------------------------------
extern "C" void kernel_launch(void* const* d_in, const int* in_sizes, int n_in,
                              void* d_out, int out_size) {
    const float* feat = (const float*)d_in[0];
    const float* Wm   = (const float*)d_in[1];
    const int*   src  = (const int*)d_in[2];
    const int*   dst  = (const int*)d_in[3];
    float* out = (float*)d_out;

    int nbE4 = (NE / 4 + 255) / 256;         // 1563
    int nbG  = (NN + 127) / 128;             // 782
    int nbA  = (NN + 7) / 8;                 // 12500

    k_deg<<<nbE4, 256>>>(dst);
    k_scan<<<SCAN_NB, 256>>>();
    k_scatter<<<nbE4, 256>>>(src, dst);
    k_gemm<<<nbG, 256>>>(feat, Wm);
    k_aggregate<<<nbA, 256>>>(out);
}

// round 8
// speedup vs baseline: 1.0748x; 1.0748x over previous
#include <cuda_runtime.h>
#include <cuda_bf16.h>
#include <math_constants.h>

// Problem shape (fixed by dataset)
#define NN 100000
#define NE 1600000
#define INF_ 128
#define OUTF 64
#define SCAN_NB 391          // ceil(NN/256)

// ---------------- device scratch (static: no runtime allocation) -------------
// NOTE lifecycle: g_deg is zero at every kernel_launch entry — zero-initialized
// at load, and re-zeroed by k_aggregate at the end of every executed call
// (graph capture does not execute, so the invariant holds across replays).
__device__ float g_ft[(size_t)NN * OUTF];       // projected features  [N,64]
__device__ int   g_deg[NN];                     // in-degree histogram
__device__ int   g_offs[NN + 1];                // CSR offsets by dst
__device__ int   g_cursor[NN];                  // scatter cursors
__device__ int   g_csr_src[NE];                 // src node per CSR slot
__device__ unsigned long long g_state[SCAN_NB]; // lookback: (status<<32)|sum

__device__ __forceinline__ int clampidx(int v) {
    unsigned u = (unsigned)v;
    return (u < (unsigned)NN) ? v : 0;
}

// packed f32x2 helpers (Blackwell: FFMA2 only reachable from PTX)
__device__ __forceinline__ unsigned long long pack2(float lo, float hi) {
    unsigned long long r;
    asm("mov.b64 %0, {%1, %2};" : "=l"(r) : "f"(lo), "f"(hi));
    return r;
}
__device__ __forceinline__ void unpack2(unsigned long long v, float& lo, float& hi) {
    asm("mov.b64 {%0, %1}, %2;" : "=f"(lo), "=f"(hi) : "l"(v));
}
__device__ __forceinline__ void fma2(unsigned long long& d,
                                     unsigned long long a, unsigned long long b) {
    asm("fma.rn.f32x2 %0, %1, %2, %0;" : "+l"(d) : "l"(a), "l"(b));
}

// ---------------- K1: in-degree histogram + scan-state reset -----------------
__global__ __launch_bounds__(256) void k_deg(const int* __restrict__ dst) {
    int t = blockIdx.x * blockDim.x + threadIdx.x;
    if (t < SCAN_NB) g_state[t] = 0ull;       // consumed by k_scan (next launch)
    if (t >= NE / 4) return;
    int4 d4 = ((const int4*)dst)[t];
    atomicAdd(&g_deg[clampidx(d4.x)], 1);
    atomicAdd(&g_deg[clampidx(d4.y)], 1);
    atomicAdd(&g_deg[clampidx(d4.z)], 1);
    atomicAdd(&g_deg[clampidx(d4.w)], 1);
}

// ---------------- K2: single-pass decoupled-lookback exclusive scan ----------
__global__ __launch_bounds__(256) void k_scan() {
    __shared__ int wsum[8];
    __shared__ int bprefix;
    int b = blockIdx.x;
    int tid = threadIdx.x;
    int lane = tid & 31;
    int wid = tid >> 5;
    int i = b * 256 + tid;

    int v = (i < NN) ? g_deg[i] : 0;
    int x = v;
#pragma unroll
    for (int o = 1; o < 32; o <<= 1) {
        int t = __shfl_up_sync(0xffffffffu, x, o);
        if (lane >= o) x += t;
    }
    if (lane == 31) wsum[wid] = x;
    __syncthreads();
    if (wid == 0) {
        int y = (lane < 8) ? wsum[lane] : 0;
#pragma unroll
        for (int o = 1; o < 8; o <<= 1) {
            int t = __shfl_up_sync(0xffffffffu, y, o);
            if (lane >= o) y += t;
        }
        if (lane < 8) wsum[lane] = y;
    }
    __syncthreads();
    int incl = x + ((wid > 0) ? wsum[wid - 1] : 0);
    int btotal = wsum[7];

    if (tid == 0) {
        if (b == 0) {
            atomicExch(&g_state[0], (2ull << 32) | (unsigned)btotal);
            bprefix = 0;
        } else {
            atomicExch(&g_state[b], (1ull << 32) | (unsigned)btotal);
            long long ex = 0;
            int pred = b - 1;
            while (true) {
                unsigned long long s =
                    *((volatile unsigned long long*)&g_state[pred]);
                unsigned st = (unsigned)(s >> 32);
                if (st == 0) continue;
                ex += (unsigned)s;
                if (st == 2) break;
                pred--;
            }
            atomicExch(&g_state[b], (2ull << 32) | (unsigned)(ex + btotal));
            bprefix = (int)ex;
        }
    }
    __syncthreads();

    if (i < NN) {
        int o = bprefix + incl - v;
        g_offs[i] = o;
        g_cursor[i] = o;
    }
    if (i == 0) g_offs[NN] = NE;
}

// ---------------- K3: scatter into CSR (4 atomics batched -> 4 stores) -------
__global__ __launch_bounds__(256) void k_scatter(const int* __restrict__ src,
                                                 const int* __restrict__ dst) {
    int t = blockIdx.x * blockDim.x + threadIdx.x;
    if (t >= NE / 4) return;
    int4 s4 = ((const int4*)src)[t];
    int4 d4 = ((const int4*)dst)[t];
    int p0 = atomicAdd(&g_cursor[clampidx(d4.x)], 1);
    int p1 = atomicAdd(&g_cursor[clampidx(d4.y)], 1);
    int p2 = atomicAdd(&g_cursor[clampidx(d4.z)], 1);
    int p3 = atomicAdd(&g_cursor[clampidx(d4.w)], 1);
    g_csr_src[p0] = clampidx(s4.x);
    g_csr_src[p1] = clampidx(s4.y);
    g_csr_src[p2] = clampidx(s4.z);
    g_csr_src[p3] = clampidx(s4.w);
}

// ---------------- K4: ft = feat @ W  (64x64 tile, 4x4/thread, FFMA2) ---------
// 4 blocks/SM (32 warps) — occupancy is the binding constraint, not tile size.
__global__ __launch_bounds__(256, 4) void k_gemm(const float* __restrict__ feat,
                                                 const float* __restrict__ Wm) {
    __shared__ float wsm[INF_ * OUTF];   // 32 KB
    int tid = threadIdx.x;

    for (int i = tid; i < (INF_ * OUTF) / 4; i += 256)
        ((float4*)wsm)[i] = ((const float4*)Wm)[i];
    __syncthreads();

    int row0 = blockIdx.x * 64 + (tid >> 4) * 4;   // 4 rows
    int c0 = (tid & 15) * 4;                       // 4 cols

    int r[4];
#pragma unroll
    for (int i = 0; i < 4; i++) r[i] = (row0 + i < NN) ? row0 + i : 0;

    unsigned long long acc[4][2];
#pragma unroll
    for (int i = 0; i < 4; i++) { acc[i][0] = 0ull; acc[i][1] = 0ull; }

#pragma unroll 2
    for (int kk = 0; kk < INF_ / 4; kk++) {
        float4 fr[4];
#pragma unroll
        for (int i = 0; i < 4; i++)
            fr[i] = ((const float4*)(feat + (size_t)r[i] * INF_))[kk];
#pragma unroll
        for (int j = 0; j < 4; j++) {
            float4 w4 = *(const float4*)(wsm + (kk * 4 + j) * OUTF + c0);
            unsigned long long bxy = pack2(w4.x, w4.y);
            unsigned long long bzw = pack2(w4.z, w4.w);
#pragma unroll
            for (int i = 0; i < 4; i++) {
                float f = (j == 0) ? fr[i].x : (j == 1) ? fr[i].y
                         : (j == 2) ? fr[i].z : fr[i].w;
                unsigned long long a2 = pack2(f, f);
                fma2(acc[i][0], a2, bxy);
                fma2(acc[i][1], a2, bzw);
            }
        }
    }

#pragma unroll
    for (int i = 0; i < 4; i++) {
        int row = row0 + i;
        if (row < NN) {
            float4 o;
            unpack2(acc[i][0], o.x, o.y);
            unpack2(acc[i][1], o.z, o.w);
            *(float4*)(g_ft + (size_t)row * OUTF + c0) = o;
        }
    }
}

// ---------------- K5: fused score + ONLINE softmax + aggregation -------------
// One warp per node; lane l owns output dims [2l, 2l+1].
// Warp dot-reduce via half-warp fold: 6 SHFLs per 2 edges; 4-edge unroll.
__global__ __launch_bounds__(256) void k_aggregate(float* __restrict__ out) {
    int w = threadIdx.x >> 5;
    int lane = threadIdx.x & 31;
    int node = blockIdx.x * 8 + w;
    if (node >= NN) return;

    int lo = g_offs[node];
    int hi = g_offs[node + 1];
    if (lane == 0) g_deg[node] = 0;          // reset for next replay

    float2 df = *(const float2*)(g_ft + (size_t)node * OUTF + lane * 2);

    float m = -CUDART_INF_F;
    float s = 0.f;
    float2 acc = make_float2(0.f, 0.f);
    bool hi16 = (lane & 16) != 0;

    int i = lo;
    for (; i + 3 < hi; i += 4) {
        int s0 = g_csr_src[i];
        int s1 = g_csr_src[i + 1];
        int s2 = g_csr_src[i + 2];
        int s3 = g_csr_src[i + 3];
        float2 f0 = *(const float2*)(g_ft + (size_t)s0 * OUTF + lane * 2);
        float2 f1 = *(const float2*)(g_ft + (size_t)s1 * OUTF + lane * 2);
        float2 f2 = *(const float2*)(g_ft + (size_t)s2 * OUTF + lane * 2);
        float2 f3 = *(const float2*)(g_ft + (size_t)s3 * OUTF + lane * 2);
        float p0 = f0.x * df.x + f0.y * df.y;
        float p1 = f1.x * df.x + f1.y * df.y;
        float p2 = f2.x * df.x + f2.y * df.y;
        float p3 = f3.x * df.x + f3.y * df.y;

        // fold chains: low half reduces even edge, high half odd edge
        float uA = hi16 ? p1 : p0;
        float uB = hi16 ? p3 : p2;
        uA += __shfl_xor_sync(0xffffffffu, hi16 ? p0 : p1, 16);
        uB += __shfl_xor_sync(0xffffffffu, hi16 ? p2 : p3, 16);
#pragma unroll
        for (int o = 8; o; o >>= 1) {
            uA += __shfl_xor_sync(0xffffffffu, uA, o);
            uB += __shfl_xor_sync(0xffffffffu, uB, o);
        }
        float oA = __shfl_xor_sync(0xffffffffu, uA, 16);
        float oB = __shfl_xor_sync(0xffffffffu, uB, 16);
        float a0 = hi16 ? oA : uA;
        float a1 = hi16 ? uA : oA;
        float a2 = hi16 ? oB : uB;
        float a3 = hi16 ? uB : oB;

        float mn = fmaxf(fmaxf(a0, a1), fmaxf(a2, a3));
        if (mn > m) {                          // warp-uniform branch
            float rsc = __expf(m - mn);        // first hit: exp(-inf)=0
            s *= rsc; acc.x *= rsc; acc.y *= rsc;
            m = mn;
        }
        float w0 = __expf(a0 - m);
        float w1 = __expf(a1 - m);
        float w2 = __expf(a2 - m);
        float w3 = __expf(a3 - m);
        s += (w0 + w1) + (w2 + w3);
        acc.x += w0 * f0.x + w1 * f1.x + w2 * f2.x + w3 * f3.x;
        acc.y += w0 * f0.y + w1 * f1.y + w2 * f2.y + w3 * f3.y;
    }
    // remainder (0-3 edges): plain butterfly
    for (; i < hi; i++) {
        int s0 = g_csr_src[i];
        float2 f0 = *(const float2*)(g_ft + (size_t)s0 * OUTF + lane * 2);
        float p0 = f0.x * df.x + f0.y * df.y;
#pragma unroll
        for (int o = 16; o; o >>= 1) p0 += __shfl_xor_sync(0xffffffffu, p0, o);
        if (p0 > m) {
            float rsc = __expf(m - p0);
            s *= rsc; acc.x *= rsc; acc.y *= rsc;
            m = p0;
        }
        float w0 = __expf(p0 - m);
        s += w0;
        acc.x += w0 * f0.x;
        acc.y += w0 * f0.y;
    }

    if (hi > lo) {
        float inv = 1.f / s;
        acc.x *= inv;
        acc.y *= inv;
    }
    *(float2*)(out + (size_t)node * OUTF + lane * 2) = acc;
}

// ---------------- launch ------------------------------------------------------
extern "C" void kernel_launch(void* const* d_in, const int* in_sizes, int n_in,
                              void* d_out, int out_size) {
    const float* feat = (const float*)d_in[0];
    const float* Wm   = (const float*)d_in[1];
    const int*   src  = (const int*)d_in[2];
    const int*   dst  = (const int*)d_in[3];
    float* out = (float*)d_out;

    int nbE4 = (NE / 4 + 255) / 256;         // 1563
    int nbG  = (NN + 63) / 64;               // 1563
    int nbA  = (NN + 7) / 8;                 // 12500

    k_deg<<<nbE4, 256>>>(dst);
    k_scan<<<SCAN_NB, 256>>>();
    k_scatter<<<nbE4, 256>>>(src, dst);
    k_gemm<<<nbG, 256>>>(feat, Wm);
    k_aggregate<<<nbA, 256>>>(out);
}

// round 9
// speedup vs baseline: 1.1732x; 1.0916x over previous
#include <cuda_runtime.h>
#include <cuda_bf16.h>
#include <math_constants.h>

// Problem shape (fixed by dataset)
#define NN 100000
#define NE 1600000
#define INF_ 128
#define OUTF 64
#define SCAN_NB 391          // ceil(NN/256)

// ---------------- device scratch (static: no runtime allocation) -------------
// NOTE lifecycle: g_deg is zero at every kernel_launch entry — zero-initialized
// at load, and re-zeroed by k_aggregate at the end of every executed call
// (graph capture does not execute, so the invariant holds across replays).
__device__ float g_ft[(size_t)NN * OUTF];       // projected features  [N,64]
__device__ int   g_deg[NN];                     // in-degree histogram
__device__ int   g_offs[NN + 1];                // CSR offsets by dst
__device__ int   g_cursor[NN];                  // scatter cursors
__device__ int   g_csr_src[NE];                 // src node per CSR slot
__device__ unsigned long long g_state[SCAN_NB]; // lookback: (status<<32)|sum

__device__ __forceinline__ int clampidx(int v) {
    unsigned u = (unsigned)v;
    return (u < (unsigned)NN) ? v : 0;
}

// packed f32x2 helpers (Blackwell: FFMA2 only reachable from PTX)
__device__ __forceinline__ unsigned long long pack2(float lo, float hi) {
    unsigned long long r;
    asm("mov.b64 %0, {%1, %2};" : "=l"(r) : "f"(lo), "f"(hi));
    return r;
}
__device__ __forceinline__ void unpack2(unsigned long long v, float& lo, float& hi) {
    asm("mov.b64 {%0, %1}, %2;" : "=f"(lo), "=f"(hi) : "l"(v));
}
__device__ __forceinline__ void fma2(unsigned long long& d,
                                     unsigned long long a, unsigned long long b) {
    asm("fma.rn.f32x2 %0, %1, %2, %0;" : "+l"(d) : "l"(a), "l"(b));
}

// ---------------- K1: in-degree histogram + scan-state reset -----------------
__global__ __launch_bounds__(256) void k_deg(const int* __restrict__ dst) {
    int t = blockIdx.x * blockDim.x + threadIdx.x;
    if (t < SCAN_NB) g_state[t] = 0ull;       // consumed by k_scan (next launch)
    if (t >= NE / 4) return;
    int4 d4 = ((const int4*)dst)[t];
    atomicAdd(&g_deg[clampidx(d4.x)], 1);
    atomicAdd(&g_deg[clampidx(d4.y)], 1);
    atomicAdd(&g_deg[clampidx(d4.z)], 1);
    atomicAdd(&g_deg[clampidx(d4.w)], 1);
}

// ---------------- K2: single-pass decoupled-lookback exclusive scan ----------
__global__ __launch_bounds__(256) void k_scan() {
    __shared__ int wsum[8];
    __shared__ int bprefix;
    int b = blockIdx.x;
    int tid = threadIdx.x;
    int lane = tid & 31;
    int wid = tid >> 5;
    int i = b * 256 + tid;

    int v = (i < NN) ? g_deg[i] : 0;
    int x = v;
#pragma unroll
    for (int o = 1; o < 32; o <<= 1) {
        int t = __shfl_up_sync(0xffffffffu, x, o);
        if (lane >= o) x += t;
    }
    if (lane == 31) wsum[wid] = x;
    __syncthreads();
    if (wid == 0) {
        int y = (lane < 8) ? wsum[lane] : 0;
#pragma unroll
        for (int o = 1; o < 8; o <<= 1) {
            int t = __shfl_up_sync(0xffffffffu, y, o);
            if (lane >= o) y += t;
        }
        if (lane < 8) wsum[lane] = y;
    }
    __syncthreads();
    int incl = x + ((wid > 0) ? wsum[wid - 1] : 0);
    int btotal = wsum[7];

    if (tid == 0) {
        if (b == 0) {
            atomicExch(&g_state[0], (2ull << 32) | (unsigned)btotal);
            bprefix = 0;
        } else {
            atomicExch(&g_state[b], (1ull << 32) | (unsigned)btotal);
            long long ex = 0;
            int pred = b - 1;
            while (true) {
                unsigned long long s =
                    *((volatile unsigned long long*)&g_state[pred]);
                unsigned st = (unsigned)(s >> 32);
                if (st == 0) continue;
                ex += (unsigned)s;
                if (st == 2) break;
                pred--;
            }
            atomicExch(&g_state[b], (2ull << 32) | (unsigned)(ex + btotal));
            bprefix = (int)ex;
        }
    }
    __syncthreads();

    if (i < NN) {
        int o = bprefix + incl - v;
        g_offs[i] = o;
        g_cursor[i] = o;
    }
    if (i == 0) g_offs[NN] = NE;
}

// ---------------- K3: scatter into CSR (4 atomics batched -> 4 stores) -------
__global__ __launch_bounds__(256) void k_scatter(const int* __restrict__ src,
                                                 const int* __restrict__ dst) {
    int t = blockIdx.x * blockDim.x + threadIdx.x;
    if (t >= NE / 4) return;
    int4 s4 = ((const int4*)src)[t];
    int4 d4 = ((const int4*)dst)[t];
    int p0 = atomicAdd(&g_cursor[clampidx(d4.x)], 1);
    int p1 = atomicAdd(&g_cursor[clampidx(d4.y)], 1);
    int p2 = atomicAdd(&g_cursor[clampidx(d4.z)], 1);
    int p3 = atomicAdd(&g_cursor[clampidx(d4.w)], 1);
    g_csr_src[p0] = clampidx(s4.x);
    g_csr_src[p1] = clampidx(s4.y);
    g_csr_src[p2] = clampidx(s4.z);
    g_csr_src[p3] = clampidx(s4.w);
}

// ---------------- K4: ft = feat @ W  (64x64 tile, 4x4/thread, FFMA2) ---------
// 4 blocks/SM (32 warps) — occupancy is the binding constraint, not tile size.
__global__ __launch_bounds__(256, 4) void k_gemm(const float* __restrict__ feat,
                                                 const float* __restrict__ Wm) {
    __shared__ float wsm[INF_ * OUTF];   // 32 KB
    int tid = threadIdx.x;

    for (int i = tid; i < (INF_ * OUTF) / 4; i += 256)
        ((float4*)wsm)[i] = ((const float4*)Wm)[i];
    __syncthreads();

    int row0 = blockIdx.x * 64 + (tid >> 4) * 4;   // 4 rows
    int c0 = (tid & 15) * 4;                       // 4 cols

    int r[4];
#pragma unroll
    for (int i = 0; i < 4; i++) r[i] = (row0 + i < NN) ? row0 + i : 0;

    unsigned long long acc[4][2];
#pragma unroll
    for (int i = 0; i < 4; i++) { acc[i][0] = 0ull; acc[i][1] = 0ull; }

#pragma unroll 2
    for (int kk = 0; kk < INF_ / 4; kk++) {
        float4 fr[4];
#pragma unroll
        for (int i = 0; i < 4; i++)
            fr[i] = ((const float4*)(feat + (size_t)r[i] * INF_))[kk];
#pragma unroll
        for (int j = 0; j < 4; j++) {
            float4 w4 = *(const float4*)(wsm + (kk * 4 + j) * OUTF + c0);
            unsigned long long bxy = pack2(w4.x, w4.y);
            unsigned long long bzw = pack2(w4.z, w4.w);
#pragma unroll
            for (int i = 0; i < 4; i++) {
                float f = (j == 0) ? fr[i].x : (j == 1) ? fr[i].y
                         : (j == 2) ? fr[i].z : fr[i].w;
                unsigned long long a2 = pack2(f, f);
                fma2(acc[i][0], a2, bxy);
                fma2(acc[i][1], a2, bzw);
            }
        }
    }

#pragma unroll
    for (int i = 0; i < 4; i++) {
        int row = row0 + i;
        if (row < NN) {
            float4 o;
            unpack2(acc[i][0], o.x, o.y);
            unpack2(acc[i][1], o.z, o.w);
            *(float4*)(g_ft + (size_t)row * OUTF + c0) = o;
        }
    }
}

// ---------------- K5: fused score + ONLINE softmax + aggregation -------------
// One warp per node; lane l owns output dims [2l, 2l+1].
// Warp dot-reduce via half-warp fold: 6 SHFLs per 2 edges; 4-edge unroll.
__global__ __launch_bounds__(256) void k_aggregate(float* __restrict__ out) {
    int w = threadIdx.x >> 5;
    int lane = threadIdx.x & 31;
    int node = blockIdx.x * 8 + w;
    if (node >= NN) return;

    int lo = g_offs[node];
    int hi = g_offs[node + 1];
    if (lane == 0) g_deg[node] = 0;          // reset for next replay

    float2 df = *(const float2*)(g_ft + (size_t)node * OUTF + lane * 2);

    float m = -CUDART_INF_F;
    float s = 0.f;
    float2 acc = make_float2(0.f, 0.f);
    bool hi16 = (lane & 16) != 0;

    int i = lo;
    for (; i + 3 < hi; i += 4) {
        int s0 = g_csr_src[i];
        int s1 = g_csr_src[i + 1];
        int s2 = g_csr_src[i + 2];
        int s3 = g_csr_src[i + 3];
        float2 f0 = *(const float2*)(g_ft + (size_t)s0 * OUTF + lane * 2);
        float2 f1 = *(const float2*)(g_ft + (size_t)s1 * OUTF + lane * 2);
        float2 f2 = *(const float2*)(g_ft + (size_t)s2 * OUTF + lane * 2);
        float2 f3 = *(const float2*)(g_ft + (size_t)s3 * OUTF + lane * 2);
        float p0 = f0.x * df.x + f0.y * df.y;
        float p1 = f1.x * df.x + f1.y * df.y;
        float p2 = f2.x * df.x + f2.y * df.y;
        float p3 = f3.x * df.x + f3.y * df.y;

        // fold chains: low half reduces even edge, high half odd edge
        float uA = hi16 ? p1 : p0;
        float uB = hi16 ? p3 : p2;
        uA += __shfl_xor_sync(0xffffffffu, hi16 ? p0 : p1, 16);
        uB += __shfl_xor_sync(0xffffffffu, hi16 ? p2 : p3, 16);
#pragma unroll
        for (int o = 8; o; o >>= 1) {
            uA += __shfl_xor_sync(0xffffffffu, uA, o);
            uB += __shfl_xor_sync(0xffffffffu, uB, o);
        }
        float oA = __shfl_xor_sync(0xffffffffu, uA, 16);
        float oB = __shfl_xor_sync(0xffffffffu, uB, 16);
        float a0 = hi16 ? oA : uA;
        float a1 = hi16 ? uA : oA;
        float a2 = hi16 ? oB : uB;
        float a3 = hi16 ? uB : oB;

        float mn = fmaxf(fmaxf(a0, a1), fmaxf(a2, a3));
        if (mn > m) {                          // warp-uniform branch
            float rsc = __expf(m - mn);        // first hit: exp(-inf)=0
            s *= rsc; acc.x *= rsc; acc.y *= rsc;
            m = mn;
        }
        float w0 = __expf(a0 - m);
        float w1 = __expf(a1 - m);
        float w2 = __expf(a2 - m);
        float w3 = __expf(a3 - m);
        s += (w0 + w1) + (w2 + w3);
        acc.x += w0 * f0.x + w1 * f1.x + w2 * f2.x + w3 * f3.x;
        acc.y += w0 * f0.y + w1 * f1.y + w2 * f2.y + w3 * f3.y;
    }
    // remainder (0-3 edges): plain butterfly
    for (; i < hi; i++) {
        int s0 = g_csr_src[i];
        float2 f0 = *(const float2*)(g_ft + (size_t)s0 * OUTF + lane * 2);
        float p0 = f0.x * df.x + f0.y * df.y;
#pragma unroll
        for (int o = 16; o; o >>= 1) p0 += __shfl_xor_sync(0xffffffffu, p0, o);
        if (p0 > m) {
            float rsc = __expf(m - p0);
            s *= rsc; acc.x *= rsc; acc.y *= rsc;
            m = p0;
        }
        float w0 = __expf(p0 - m);
        s += w0;
        acc.x += w0 * f0.x;
        acc.y += w0 * f0.y;
    }

    if (hi > lo) {
        float inv = 1.f / s;
        acc.x *= inv;
        acc.y *= inv;
    }
    *(float2*)(out + (size_t)node * OUTF + lane * 2) = acc;
}

// ---------------- launch ------------------------------------------------------
// Two independent chains overlapped via capture-legal stream fork:
//   main:  deg -> scan -> scatter ──┐
//   side:  gemm ────────────────────┴─> aggregate (main)
// Stream/events created once on the first (uncaptured) call; every call does
// identical deterministic work.
extern "C" void kernel_launch(void* const* d_in, const int* in_sizes, int n_in,
                              void* d_out, int out_size) {
    const float* feat = (const float*)d_in[0];
    const float* Wm   = (const float*)d_in[1];
    const int*   src  = (const int*)d_in[2];
    const int*   dst  = (const int*)d_in[3];
    float* out = (float*)d_out;

    int nbE4 = (NE / 4 + 255) / 256;         // 1563
    int nbG  = (NN + 63) / 64;               // 1563
    int nbA  = (NN + 7) / 8;                 // 12500

    static cudaStream_t s2 = nullptr;
    static cudaEvent_t evFork = nullptr, evJoin = nullptr;
    static bool initTried = false;
    if (!initTried) {
        initTried = true;
        if (cudaStreamCreateWithFlags(&s2, cudaStreamNonBlocking) != cudaSuccess)
            s2 = nullptr;
        if (s2) {
            cudaEventCreateWithFlags(&evFork, cudaEventDisableTiming);
            cudaEventCreateWithFlags(&evJoin, cudaEventDisableTiming);
        }
    }

    if (s2) {
        // fork: side stream joins the capture DAG via event dependency
        cudaEventRecord(evFork, 0);
        cudaStreamWaitEvent(s2, evFork, 0);
        k_gemm<<<nbG, 256, 0, s2>>>(feat, Wm);

        k_deg<<<nbE4, 256>>>(dst);
        k_scan<<<SCAN_NB, 256>>>();
        k_scatter<<<nbE4, 256>>>(src, dst);

        // join: aggregate needs both g_ft (side) and CSR (main)
        cudaEventRecord(evJoin, s2);
        cudaStreamWaitEvent(0, evJoin, 0);
        k_aggregate<<<nbA, 256>>>(out);
    } else {
        // serial fallback
        k_deg<<<nbE4, 256>>>(dst);
        k_scan<<<SCAN_NB, 256>>>();
        k_scatter<<<nbE4, 256>>>(src, dst);
        k_gemm<<<nbG, 256>>>(feat, Wm);
        k_aggregate<<<nbA, 256>>>(out);
    }
}

// round 12
// speedup vs baseline: 1.2488x; 1.0645x over previous
#include <cuda_runtime.h>
#include <cuda_bf16.h>
#include <math_constants.h>

// Problem shape (fixed by dataset)
#define NN 100000
#define NE 1600000
#define INF_ 128
#define OUTF 64
#define SCAN_NB 391          // ceil(NN/256)

// ---------------- device scratch (static: no runtime allocation) -------------
// NOTE lifecycle: g_deg is zero at every kernel_launch entry — zero-initialized
// at load, and re-zeroed by k_aggregate at the end of every executed call
// (graph capture does not execute, so the invariant holds across replays).
__device__ float g_ft[(size_t)NN * OUTF];       // projected features  [N,64]
__device__ int   g_deg[NN];                     // in-degree histogram
__device__ int   g_offs[NN + 1];                // CSR offsets by dst
__device__ int   g_cursor[NN];                  // scatter cursors
__device__ int   g_csr_src[NE];                 // src node per CSR slot
__device__ unsigned long long g_state[SCAN_NB]; // lookback: (status<<32)|sum

__device__ __forceinline__ int clampidx(int v) {
    unsigned u = (unsigned)v;
    return (u < (unsigned)NN) ? v : 0;
}

// packed f32x2 helpers (Blackwell: FFMA2 only reachable from PTX)
__device__ __forceinline__ unsigned long long pack2(float lo, float hi) {
    unsigned long long r;
    asm("mov.b64 %0, {%1, %2};" : "=l"(r) : "f"(lo), "f"(hi));
    return r;
}
__device__ __forceinline__ void unpack2(unsigned long long v, float& lo, float& hi) {
    asm("mov.b64 {%0, %1}, %2;" : "=f"(lo), "=f"(hi) : "l"(v));
}
__device__ __forceinline__ void fma2(unsigned long long& d,
                                     unsigned long long a, unsigned long long b) {
    asm("fma.rn.f32x2 %0, %1, %2, %0;" : "+l"(d) : "l"(a), "l"(b));
}

// ---------------- K1: in-degree histogram + scan-state reset -----------------
__global__ __launch_bounds__(256) void k_deg(const int* __restrict__ dst) {
    int t = blockIdx.x * blockDim.x + threadIdx.x;
    if (t < SCAN_NB) g_state[t] = 0ull;       // consumed by k_scan (next launch)
    if (t >= NE / 4) return;
    int4 d4 = ((const int4*)dst)[t];
    atomicAdd(&g_deg[clampidx(d4.x)], 1);
    atomicAdd(&g_deg[clampidx(d4.y)], 1);
    atomicAdd(&g_deg[clampidx(d4.z)], 1);
    atomicAdd(&g_deg[clampidx(d4.w)], 1);
}

// ---------------- K2: single-pass decoupled-lookback exclusive scan ----------
__global__ __launch_bounds__(256) void k_scan() {
    __shared__ int wsum[8];
    __shared__ int bprefix;
    int b = blockIdx.x;
    int tid = threadIdx.x;
    int lane = tid & 31;
    int wid = tid >> 5;
    int i = b * 256 + tid;

    int v = (i < NN) ? g_deg[i] : 0;
    int x = v;
#pragma unroll
    for (int o = 1; o < 32; o <<= 1) {
        int t = __shfl_up_sync(0xffffffffu, x, o);
        if (lane >= o) x += t;
    }
    if (lane == 31) wsum[wid] = x;
    __syncthreads();
    if (wid == 0) {
        int y = (lane < 8) ? wsum[lane] : 0;
#pragma unroll
        for (int o = 1; o < 8; o <<= 1) {
            int t = __shfl_up_sync(0xffffffffu, y, o);
            if (lane >= o) y += t;
        }
        if (lane < 8) wsum[lane] = y;
    }
    __syncthreads();
    int incl = x + ((wid > 0) ? wsum[wid - 1] : 0);
    int btotal = wsum[7];

    if (tid == 0) {
        if (b == 0) {
            atomicExch(&g_state[0], (2ull << 32) | (unsigned)btotal);
            bprefix = 0;
        } else {
            atomicExch(&g_state[b], (1ull << 32) | (unsigned)btotal);
            long long ex = 0;
            int pred = b - 1;
            while (true) {
                unsigned long long s =
                    *((volatile unsigned long long*)&g_state[pred]);
                unsigned st = (unsigned)(s >> 32);
                if (st == 0) continue;
                ex += (unsigned)s;
                if (st == 2) break;
                pred--;
            }
            atomicExch(&g_state[b], (2ull << 32) | (unsigned)(ex + btotal));
            bprefix = (int)ex;
        }
    }
    __syncthreads();

    if (i < NN) {
        int o = bprefix + incl - v;
        g_offs[i] = o;
        g_cursor[i] = o;
    }
    if (i == 0) g_offs[NN] = NE;
}

// ---------------- K3: scatter into CSR (4 atomics batched -> 4 stores) -------
__global__ __launch_bounds__(256) void k_scatter(const int* __restrict__ src,
                                                 const int* __restrict__ dst) {
    int t = blockIdx.x * blockDim.x + threadIdx.x;
    if (t >= NE / 4) return;
    int4 s4 = ((const int4*)src)[t];
    int4 d4 = ((const int4*)dst)[t];
    int p0 = atomicAdd(&g_cursor[clampidx(d4.x)], 1);
    int p1 = atomicAdd(&g_cursor[clampidx(d4.y)], 1);
    int p2 = atomicAdd(&g_cursor[clampidx(d4.z)], 1);
    int p3 = atomicAdd(&g_cursor[clampidx(d4.w)], 1);
    g_csr_src[p0] = clampidx(s4.x);
    g_csr_src[p1] = clampidx(s4.y);
    g_csr_src[p2] = clampidx(s4.z);
    g_csr_src[p3] = clampidx(s4.w);
}

// ---------------- K4: ft = feat @ W  (128x64 tile, 8 rows x 4 cols/thread) ---
// More ROWS per thread amortizes the W LDS (4 LDS.128 now feed 128 FMAs,
// halving crossbar work per FMA vs 4x4). (256,3) keeps 24 warps/SM.
__global__ __launch_bounds__(256, 3) void k_gemm(const float* __restrict__ feat,
                                                 const float* __restrict__ Wm) {
    __shared__ float wsm[INF_ * OUTF];   // 32 KB
    int tid = threadIdx.x;

    for (int i = tid; i < (INF_ * OUTF) / 4; i += 256)
        ((float4*)wsm)[i] = ((const float4*)Wm)[i];
    __syncthreads();

    int rg = tid >> 4;                         // 0..15 row group (8 rows each)
    int c0 = (tid & 15) * 4;                   // 4 cols
    int row0 = blockIdx.x * 128 + rg * 8;

    int r[8];
#pragma unroll
    for (int i = 0; i < 8; i++) r[i] = (row0 + i < NN) ? row0 + i : 0;

    unsigned long long acc[8][2];
#pragma unroll
    for (int i = 0; i < 8; i++) { acc[i][0] = 0ull; acc[i][1] = 0ull; }

    for (int kk = 0; kk < INF_ / 4; kk++) {
        float4 fr[8];
#pragma unroll
        for (int i = 0; i < 8; i++)
            fr[i] = ((const float4*)(feat + (size_t)r[i] * INF_))[kk];
#pragma unroll
        for (int j = 0; j < 4; j++) {
            float4 w4 = *(const float4*)(wsm + (kk * 4 + j) * OUTF + c0);
            unsigned long long bxy = pack2(w4.x, w4.y);
            unsigned long long bzw = pack2(w4.z, w4.w);
#pragma unroll
            for (int i = 0; i < 8; i++) {
                float f = (j == 0) ? fr[i].x : (j == 1) ? fr[i].y
                         : (j == 2) ? fr[i].z : fr[i].w;
                unsigned long long a2 = pack2(f, f);
                fma2(acc[i][0], a2, bxy);
                fma2(acc[i][1], a2, bzw);
            }
        }
    }

#pragma unroll
    for (int i = 0; i < 8; i++) {
        int row = row0 + i;
        if (row < NN) {
            float4 o;
            unpack2(acc[i][0], o.x, o.y);
            unpack2(acc[i][1], o.z, o.w);
            *(float4*)(g_ft + (size_t)row * OUTF + c0) = o;
        }
    }
}

// ---------------- K5: fused score + ONLINE softmax + aggregation -------------
// One warp per node; lane l owns output dims [2l, 2l+1].
// Warp dot-reduce via half-warp fold: 6 SHFLs per 2 edges; 4-edge unroll.
__global__ __launch_bounds__(256) void k_aggregate(float* __restrict__ out) {
    int w = threadIdx.x >> 5;
    int lane = threadIdx.x & 31;
    int node = blockIdx.x * 8 + w;
    if (node >= NN) return;

    int lo = g_offs[node];
    int hi = g_offs[node + 1];
    if (lane == 0) g_deg[node] = 0;          // reset for next replay

    float2 df = *(const float2*)(g_ft + (size_t)node * OUTF + lane * 2);

    float m = -CUDART_INF_F;
    float s = 0.f;
    float2 acc = make_float2(0.f, 0.f);
    bool hi16 = (lane & 16) != 0;

    int i = lo;
    for (; i + 3 < hi; i += 4) {
        int s0 = g_csr_src[i];
        int s1 = g_csr_src[i + 1];
        int s2 = g_csr_src[i + 2];
        int s3 = g_csr_src[i + 3];
        float2 f0 = *(const float2*)(g_ft + (size_t)s0 * OUTF + lane * 2);
        float2 f1 = *(const float2*)(g_ft + (size_t)s1 * OUTF + lane * 2);
        float2 f2 = *(const float2*)(g_ft + (size_t)s2 * OUTF + lane * 2);
        float2 f3 = *(const float2*)(g_ft + (size_t)s3 * OUTF + lane * 2);
        float p0 = f0.x * df.x + f0.y * df.y;
        float p1 = f1.x * df.x + f1.y * df.y;
        float p2 = f2.x * df.x + f2.y * df.y;
        float p3 = f3.x * df.x + f3.y * df.y;

        // fold chains: low half reduces even edge, high half odd edge
        float uA = hi16 ? p1 : p0;
        float uB = hi16 ? p3 : p2;
        uA += __shfl_xor_sync(0xffffffffu, hi16 ? p0 : p1, 16);
        uB += __shfl_xor_sync(0xffffffffu, hi16 ? p2 : p3, 16);
#pragma unroll
        for (int o = 8; o; o >>= 1) {
            uA += __shfl_xor_sync(0xffffffffu, uA, o);
            uB += __shfl_xor_sync(0xffffffffu, uB, o);
        }
        float oA = __shfl_xor_sync(0xffffffffu, uA, 16);
        float oB = __shfl_xor_sync(0xffffffffu, uB, 16);
        float a0 = hi16 ? oA : uA;
        float a1 = hi16 ? uA : oA;
        float a2 = hi16 ? oB : uB;
        float a3 = hi16 ? uB : oB;

        float mn = fmaxf(fmaxf(a0, a1), fmaxf(a2, a3));
        if (mn > m) {                          // warp-uniform branch
            float rsc = __expf(m - mn);        // first hit: exp(-inf)=0
            s *= rsc; acc.x *= rsc; acc.y *= rsc;
            m = mn;
        }
        float w0 = __expf(a0 - m);
        float w1 = __expf(a1 - m);
        float w2 = __expf(a2 - m);
        float w3 = __expf(a3 - m);
        s += (w0 + w1) + (w2 + w3);
        acc.x += w0 * f0.x + w1 * f1.x + w2 * f2.x + w3 * f3.x;
        acc.y += w0 * f0.y + w1 * f1.y + w2 * f2.y + w3 * f3.y;
    }
    // remainder (0-3 edges): plain butterfly
    for (; i < hi; i++) {
        int s0 = g_csr_src[i];
        float2 f0 = *(const float2*)(g_ft + (size_t)s0 * OUTF + lane * 2);
        float p0 = f0.x * df.x + f0.y * df.y;
#pragma unroll
        for (int o = 16; o; o >>= 1) p0 += __shfl_xor_sync(0xffffffffu, p0, o);
        if (p0 > m) {
            float rsc = __expf(m - p0);
            s *= rsc; acc.x *= rsc; acc.y *= rsc;
            m = p0;
        }
        float w0 = __expf(p0 - m);
        s += w0;
        acc.x += w0 * f0.x;
        acc.y += w0 * f0.y;
    }

    if (hi > lo) {
        float inv = 1.f / s;
        acc.x *= inv;
        acc.y *= inv;
    }
    *(float2*)(out + (size_t)node * OUTF + lane * 2) = acc;
}

// ---------------- launch ------------------------------------------------------
// Two independent chains overlapped via capture-legal stream fork:
//   main:  deg -> scan -> scatter ──┐
//   side:  gemm ────────────────────┴─> aggregate (main)
extern "C" void kernel_launch(void* const* d_in, const int* in_sizes, int n_in,
                              void* d_out, int out_size) {
    const float* feat = (const float*)d_in[0];
    const float* Wm   = (const float*)d_in[1];
    const int*   src  = (const int*)d_in[2];
    const int*   dst  = (const int*)d_in[3];
    float* out = (float*)d_out;

    int nbE4 = (NE / 4 + 255) / 256;         // 1563
    int nbG  = (NN + 127) / 128;             // 782
    int nbA  = (NN + 7) / 8;                 // 12500

    static cudaStream_t s2 = nullptr;
    static cudaEvent_t evFork = nullptr, evJoin = nullptr;
    static bool initTried = false;
    if (!initTried) {
        initTried = true;
        if (cudaStreamCreateWithFlags(&s2, cudaStreamNonBlocking) != cudaSuccess)
            s2 = nullptr;
        if (s2) {
            cudaEventCreateWithFlags(&evFork, cudaEventDisableTiming);
            cudaEventCreateWithFlags(&evJoin, cudaEventDisableTiming);
        }
    }

    if (s2) {
        cudaEventRecord(evFork, 0);
        cudaStreamWaitEvent(s2, evFork, 0);
        k_gemm<<<nbG, 256, 0, s2>>>(feat, Wm);

        k_deg<<<nbE4, 256>>>(dst);
        k_scan<<<SCAN_NB, 256>>>();
        k_scatter<<<nbE4, 256>>>(src, dst);

        cudaEventRecord(evJoin, s2);
        cudaStreamWaitEvent(0, evJoin, 0);
        k_aggregate<<<nbA, 256>>>(out);
    } else {
        k_deg<<<nbE4, 256>>>(dst);
        k_scan<<<SCAN_NB, 256>>>();
        k_scatter<<<nbE4, 256>>>(src, dst);
        k_gemm<<<nbG, 256>>>(feat, Wm);
        k_aggregate<<<nbA, 256>>>(out);
    }
}